// round 13
// baseline (speedup 1.0000x reference)
#include <cuda_runtime.h>

#define B_      512
#define T_      4096
#define THREADS 128
#define ITEMS   2
#define TILE    (THREADS * ITEMS)   // 256 -> grid.x = 16 exact
// row offset in u64: 10r + 2*(r/2). All rows 16B-aligned; lane stride (r0=2*tid)
// = 22 u64 = 44 words == 12 (mod 32) -> LDS.128 8-lane phases conflict-free.
#define ROWOFF(r) ((r) * 10 + ((((r) >> 1)) << 1))

typedef unsigned long long u64;

// ---- packed f32x2 helpers (PTX-only path on sm_103a; ptxas won't auto-fuse) ----
__device__ __forceinline__ u64 pk(float lo, float hi) {
    u64 r; asm("mov.b64 %0,{%1,%2};" : "=l"(r) : "f"(lo), "f"(hi)); return r;
}
__device__ __forceinline__ void upk(u64 v, float& lo, float& hi) {
    asm("mov.b64 {%0,%1},%2;" : "=f"(lo), "=f"(hi) : "l"(v));
}
__device__ __forceinline__ u64 ffma2(u64 a, u64 b, u64 c) {
    u64 d; asm("fma.rn.f32x2 %0,%1,%2,%3;" : "=l"(d) : "l"(a), "l"(b), "l"(c)); return d;
}
__device__ __forceinline__ u64 fmul2(u64 a, u64 b) {
    u64 d; asm("mul.rn.f32x2 %0,%1,%2;" : "=l"(d) : "l"(a), "l"(b)); return d;
}
__device__ __forceinline__ u64 fadd2(u64 a, u64 b) {
    u64 d; asm("add.rn.f32x2 %0,%1,%2;" : "=l"(d) : "l"(a), "l"(b)); return d;
}

// ---- ALL weights in constant memory (LDC port; R7-R9: LDS offload regresses).
// Conv weights as GENUINE ic-pair packs (R11 dedup). w2 stored column-wise and
// PRE-HALVED: logits use relu(x)=0.5*(x+|x|) with the 0.5 folded into w2.
struct __align__(16) Wts {
    u64 cwn[192];  // conv weights [oc][k][c]: pair c = (w[oc,2c,k], w[oc,2c+1,k])
    u64 w1[256];   // w1 as hidden-output pairs: w1[f][j] = (w1[f,2j], w1[f,2j+1])
    u64 w2a[8];    // 0.5 * w2 col 0 pairs: (w2[2j][0], w2[2j+1][0]) / 2
    u64 w2b[8];    // 0.5 * w2 col 1 pairs: (w2[2j][1], w2[2j+1][1]) / 2
    u64 cbp[16];   // conv bias as (cb, 0) pairs
    u64 b1[8];     // b1 output pairs
    u64 b2[2];     // (b2[0], 0), (b2[1], 0) — accumulator-init folding
    u64 g[8];      // ln gamma natural pairs (2c, 2c+1)
    u64 bb[8];     // ln beta  natural pairs (2c, 2c+1)
};
__constant__ Wts cW;
__device__   Wts dStage;

__global__ void prep_kernel(const float* __restrict__ conv_w, const float* __restrict__ conv_b,
                            const float* __restrict__ w1,     const float* __restrict__ b1,
                            const float* __restrict__ w2,     const float* __restrict__ b2,
                            const float* __restrict__ ln_g,   const float* __restrict__ ln_b)
{
    const int tid = threadIdx.x;
    // conv_w is (oc, ic, k): idx = oc*24 + ic*3 + k
    for (int j = tid; j < 192; j += 128) {
        const int oc = j / 12, r = j % 12, k = r / 4, c = r % 4;
        dStage.cwn[oc * 12 + k * 4 + c] =
            pk(conv_w[oc * 24 + (2 * c) * 3 + k], conv_w[oc * 24 + (2 * c + 1) * 3 + k]);
    }
    for (int j = tid; j < 256; j += 128) {
        const int f = j / 8, q = j % 8;
        dStage.w1[j] = pk(w1[f * 16 + 2 * q], w1[f * 16 + 2 * q + 1]);
    }
    if (tid < 8)  dStage.w2a[tid] = pk(0.5f * w2[4 * tid],     0.5f * w2[4 * tid + 2]); // col 0, halved
    if (tid < 8)  dStage.w2b[tid] = pk(0.5f * w2[4 * tid + 1], 0.5f * w2[4 * tid + 3]); // col 1, halved
    if (tid < 16) dStage.cbp[tid] = pk(conv_b[tid], 0.f);
    if (tid < 8)  dStage.b1[tid]  = pk(b1[2 * tid], b1[2 * tid + 1]);
    if (tid == 0) { dStage.b2[0] = pk(b2[0], 0.f); dStage.b2[1] = pk(b2[1], 0.f); }
    if (tid < 8)  dStage.g[tid]   = pk(ln_g[2 * tid], ln_g[2 * tid + 1]);
    if (tid < 8)  dStage.bb[tid]  = pk(ln_b[2 * tid], ln_b[2 * tid + 1]);
}

__global__ __launch_bounds__(THREADS, 4)
void bimanual_kernel(const float* __restrict__ x, float* __restrict__ out)
{
    __shared__ __align__(16) u64 xs[ROWOFF(TILE + 2)];   // natural-order x tile (staggered)

    const int tid   = threadIdx.x;
    const int b     = blockIdx.y;
    const int tbase = blockIdx.x * TILE;

    // ---- stage x tile: straight 4x16B copy per row (natural channel order) ----
    for (int tt = tid; tt < TILE + 2; tt += THREADS) {
        const int t = tbase - 2 + tt;
        ulonglong2* row = (ulonglong2*)&xs[ROWOFF(tt)];
        if (t >= 0) {
            const ulonglong2* p = (const ulonglong2*)(x + ((size_t)b * T_ + t) * 16);
            row[0] = p[0]; row[1] = p[1]; row[2] = p[2]; row[3] = p[3];
        } else {
            row[0] = make_ulonglong2(0ull, 0ull);
            row[1] = make_ulonglong2(0ull, 0ull);
            row[2] = make_ulonglong2(0ull, 0ull);
            row[3] = make_ulonglong2(0ull, 0ull);
        }
    }
    __syncthreads();

    // ---- per-thread: ITEMS consecutive elements, window rows r0 .. r0+ITEMS+1 ----
    const int r0 = tid * ITEMS;

    // hidden accumulators: 8 packed output-pairs per element
    u64 hid[ITEMS][8];
    #pragma unroll
    for (int j = 0; j < 8; ++j) {
        const u64 bj = cW.b1[j];
        #pragma unroll
        for (int i = 0; i < ITEMS; ++i) hid[i][j] = bj;
    }

    // Scope the x window so it is dead after the conv loop (register pressure).
    {
        // xp[r][0..3] = L channels (ic pairs), xp[r][4..7] = R channels (ic pairs)
        u64 xp[ITEMS + 2][8];
        #pragma unroll
        for (int r = 0; r < ITEMS + 2; ++r) {
            const ulonglong2* row = (const ulonglong2*)&xs[ROWOFF(r0 + r)];
            #pragma unroll
            for (int q = 0; q < 4; ++q) {           // 4x LDS.128 per row, conflict-free
                const ulonglong2 v = row[q];
                xp[r][2 * q] = v.x; xp[r][2 * q + 1] = v.y;
            }
        }

        // ---- fused conv(+ReLU) -> rank-1 MLP update; ic-pair FFMA2, dedup LDC ----
        #pragma unroll
        for (int oc = 0; oc < 16; ++oc) {
            u64 aL[ITEMS], aR[ITEMS];
            {
                const u64 cb0 = cW.cbp[oc];          // (cb, 0): bias folds into lane-sum
                #pragma unroll
                for (int i = 0; i < ITEMS; ++i) { aL[i] = cb0; aR[i] = pk(0.f, 0.f); }
            }
            #pragma unroll
            for (int k = 0; k < 3; ++k) {
                const ulonglong2* wp = (const ulonglong2*)&cW.cwn[oc * 12 + k * 4];
                const ulonglong2 w01 = wp[0];        // LDC.128: ic-pairs 0-1
                const ulonglong2 w23 = wp[1];        // LDC.128: ic-pairs 2-3
                #pragma unroll
                for (int i = 0; i < ITEMS; ++i) {
                    aL[i] = ffma2(xp[i + k][0], w01.x, aL[i]);
                    aL[i] = ffma2(xp[i + k][1], w01.y, aL[i]);
                    aL[i] = ffma2(xp[i + k][2], w23.x, aL[i]);
                    aL[i] = ffma2(xp[i + k][3], w23.y, aL[i]);
                    aR[i] = ffma2(xp[i + k][4], w01.x, aR[i]);
                    aR[i] = ffma2(xp[i + k][5], w01.y, aR[i]);
                    aR[i] = ffma2(xp[i + k][6], w23.x, aR[i]);
                    aR[i] = ffma2(xp[i + k][7], w23.y, aR[i]);
                }
            }
            // horizontal lane-sum + bias + ReLU + splat
            u64 vl[ITEMS], vr[ITEMS];
            {
                float cb; { float z; upk(cW.cbp[oc], cb, z); }
                #pragma unroll
                for (int i = 0; i < ITEMS; ++i) {
                    float l0, l1, rr0, rr1;
                    upk(aL[i], l0, l1); upk(aR[i], rr0, rr1);
                    const float hl = fmaxf(l0 + l1, 0.f);            // cb already in l0
                    const float hr = fmaxf(rr0 + rr1 + cb, 0.f);
                    vl[i] = pk(hl, hl); vr[i] = pk(hr, hr);
                }
            }
            // rank-1 update of hidden accs: hid += hl*w1[oc,:] + hr*w1[16+oc,:]
            const ulonglong2* wlr = (const ulonglong2*)&cW.w1[oc * 8];
            const ulonglong2* wrr = (const ulonglong2*)&cW.w1[(16 + oc) * 8];
            #pragma unroll
            for (int q = 0; q < 4; ++q) {
                const ulonglong2 wl = wlr[q];         // LDC.128
                const ulonglong2 wr = wrr[q];
                #pragma unroll
                for (int i = 0; i < ITEMS; ++i) {
                    hid[i][2 * q]     = ffma2(vl[i], wl.x, ffma2(vr[i], wr.x, hid[i][2 * q]));
                    hid[i][2 * q + 1] = ffma2(vl[i], wl.y, ffma2(vr[i], wr.y, hid[i][2 * q + 1]));
                }
            }
        }
    } // xp dies here

    // ---- logits: relu(h)*w2 == (h+|h|)*(w2/2); dual packed dot-product ----
    float a0v[ITEMS], a1v[ITEMS];
    {
        u64 accA[ITEMS], accB[ITEMS];
        #pragma unroll
        for (int i = 0; i < ITEMS; ++i) { accA[i] = cW.b2[0]; accB[i] = cW.b2[1]; }
        #pragma unroll
        for (int j = 0; j < 8; ++j) {
            const u64 wa = cW.w2a[j];                 // pre-halved
            const u64 wb = cW.w2b[j];
            #pragma unroll
            for (int i = 0; i < ITEMS; ++i) {
                const u64 h    = hid[i][j];
                const u64 habs = h & 0x7FFFFFFF7FFFFFFFull;   // packed |h| (2x LOP3)
                const u64 hsum = fadd2(h, habs);              // = 2*relu(h)
                accA[i] = ffma2(hsum, wa, accA[i]);
                accB[i] = ffma2(hsum, wb, accB[i]);
            }
        }
        #pragma unroll
        for (int i = 0; i < ITEMS; ++i) {
            float aLo, aHi, bLo, bHi;
            upk(accA[i], aLo, aHi); upk(accB[i], bLo, bHi);
            const float l0 = aLo + aHi;                    // b2[0] folded in aLo
            const float l1 = bLo + bHi;                    // b2[1] folded in bLo
            const float e = __expf(l1 - l0);
            a0v[i] = 1.f / (1.f + e);
            a1v[i] = e * a0v[i];
        }
    }

    // ---- gated residual + LayerNorm(16) + stores (natural channel order) ----
    #pragma unroll
    for (int i = 0; i < ITEMS; ++i) {
        const int tglob = tbase + r0 + i;
        const ulonglong2* xrow = (const ulonglong2*)&xs[ROWOFF(r0 + i + 2)];
        const u64 sp0 = pk(1.f + a0v[i], 1.f + a0v[i]);   // L channels scale
        const u64 sp1 = pk(1.f + a1v[i], 1.f + a1v[i]);   // R channels scale
        u64 yp[8];
        u64 sum = pk(0.f, 0.f);
        #pragma unroll
        for (int q = 0; q < 4; ++q) {
            const ulonglong2 v = xrow[q];
            const u64 s = (q < 2) ? sp0 : sp1;
            yp[2 * q]     = fmul2(v.x, s);
            yp[2 * q + 1] = fmul2(v.y, s);
            sum = fadd2(sum, yp[2 * q]);
            sum = fadd2(sum, yp[2 * q + 1]);
        }
        float sE, sO; upk(sum, sE, sO);                    // even/odd channel sums
        const float mu   = (sE + sO) * 0.0625f;
        const u64   nmup = pk(-mu, -mu);
        u64 var2 = pk(0.f, 0.f);
        u64 dp[8];
        #pragma unroll
        for (int c = 0; c < 8; ++c) { dp[c] = fadd2(yp[c], nmup); var2 = ffma2(dp[c], dp[c], var2); }
        float vE, vO; upk(var2, vE, vO);
        const float rs  = rsqrtf((vE + vO) * 0.0625f + 1e-5f);
        const u64   rsp = pk(rs, rs);

        // output pairs in natural order -> direct 16B stores, no unpack shuffle
        ulonglong2* outX = (ulonglong2*)(out + ((size_t)b * T_ + tglob) * 16);
        #pragma unroll
        for (int q = 0; q < 4; ++q) {
            const u64 oA = ffma2(fmul2(dp[2 * q],     rsp), cW.g[2 * q],     cW.bb[2 * q]);
            const u64 oB = ffma2(fmul2(dp[2 * q + 1], rsp), cW.g[2 * q + 1], cW.bb[2 * q + 1]);
            outX[q] = make_ulonglong2(oA, oB);
        }
        float2* outA = (float2*)(out + (size_t)B_ * T_ * 16 + ((size_t)b * T_ + tglob) * 2);
        *outA = make_float2(a0v[i], a1v[i]);
    }
}

extern "C" void kernel_launch(void* const* d_in, const int* in_sizes, int n_in,
                              void* d_out, int out_size)
{
    const float* x      = (const float*)d_in[0];
    const float* conv_w = (const float*)d_in[1];
    const float* conv_b = (const float*)d_in[2];
    const float* w1     = (const float*)d_in[3];
    const float* b1     = (const float*)d_in[4];
    const float* w2     = (const float*)d_in[5];
    const float* b2     = (const float*)d_in[6];
    const float* ln_g   = (const float*)d_in[7];
    const float* ln_b   = (const float*)d_in[8];

    // 1) pack weights into a device staging struct
    prep_kernel<<<1, 128>>>(conv_w, conv_b, w1, b1, w2, b2, ln_g, ln_b);

    // 2) D2D copy staging -> __constant__ (async, graph-capturable memcpy node)
    void* stage_ptr = nullptr;
    cudaGetSymbolAddress(&stage_ptr, dStage);
    cudaMemcpyToSymbolAsync(cW, stage_ptr, sizeof(Wts), 0, cudaMemcpyDeviceToDevice, 0);

    // 3) main kernel
    dim3 grid(T_ / TILE, B_);
    bimanual_kernel<<<grid, THREADS>>>(x, (float*)d_out);
}

// round 14
// speedup vs baseline: 1.0027x; 1.0027x over previous
#include <cuda_runtime.h>

#define B_      512
#define T_      4096
#define THREADS 128
#define ITEMS   2
#define TILE    (THREADS * ITEMS)   // 256 -> grid.x = 16 exact
// row offset in u64: 10r + 2*(r/2). All rows 16B-aligned; lane stride (r0=2*tid)
// = 22 u64 = 44 words == 12 (mod 32) -> LDS.128 8-lane phases conflict-free.
#define ROWOFF(r) ((r) * 10 + ((((r) >> 1)) << 1))

typedef unsigned long long u64;

// ---- packed f32x2 helpers (PTX-only path on sm_103a; ptxas won't auto-fuse) ----
__device__ __forceinline__ u64 pk(float lo, float hi) {
    u64 r; asm("mov.b64 %0,{%1,%2};" : "=l"(r) : "f"(lo), "f"(hi)); return r;
}
__device__ __forceinline__ void upk(u64 v, float& lo, float& hi) {
    asm("mov.b64 {%0,%1},%2;" : "=f"(lo), "=f"(hi) : "l"(v));
}
__device__ __forceinline__ u64 ffma2(u64 a, u64 b, u64 c) {
    u64 d; asm("fma.rn.f32x2 %0,%1,%2,%3;" : "=l"(d) : "l"(a), "l"(b), "l"(c)); return d;
}
__device__ __forceinline__ u64 fmul2(u64 a, u64 b) {
    u64 d; asm("mul.rn.f32x2 %0,%1,%2;" : "=l"(d) : "l"(a), "l"(b)); return d;
}
__device__ __forceinline__ u64 fadd2(u64 a, u64 b) {
    u64 d; asm("add.rn.f32x2 %0,%1,%2;" : "=l"(d) : "l"(a), "l"(b)); return d;
}

// ---- ALL weights in constant memory (LDC port; R7-R9: LDS offload regresses).
// Conv weights as GENUINE ic-pair packs (R11 dedup). w2 column-wise, PRE-HALVED
// for the relu(x)=0.5*(x+|x|) logits identity. Prep kernel writes DIRECTLY to
// this symbol's device backing (graph: 2 nodes instead of 3).
struct __align__(16) Wts {
    u64 cwn[192];  // conv weights [oc][k][c]: pair c = (w[oc,2c,k], w[oc,2c+1,k])
    u64 w1[256];   // w1 as hidden-output pairs: w1[f][j] = (w1[f,2j], w1[f,2j+1])
    u64 w2a[8];    // 0.5 * w2 col 0 pairs
    u64 w2b[8];    // 0.5 * w2 col 1 pairs
    u64 cbp[16];   // conv bias as (cb, 0) pairs (inits BOTH stream accumulators)
    u64 b1[8];     // b1 output pairs
    u64 b2[2];     // (b2[0], 0), (b2[1], 0) — accumulator-init folding
    u64 g[8];      // ln gamma natural pairs (2c, 2c+1)
    u64 bb[8];     // ln beta  natural pairs (2c, 2c+1)
};
__constant__ Wts cW;

__global__ void prep_kernel(Wts* __restrict__ dst,
                            const float* __restrict__ conv_w, const float* __restrict__ conv_b,
                            const float* __restrict__ w1,     const float* __restrict__ b1,
                            const float* __restrict__ w2,     const float* __restrict__ b2,
                            const float* __restrict__ ln_g,   const float* __restrict__ ln_b)
{
    const int tid = threadIdx.x;
    // conv_w is (oc, ic, k): idx = oc*24 + ic*3 + k
    for (int j = tid; j < 192; j += 128) {
        const int oc = j / 12, r = j % 12, k = r / 4, c = r % 4;
        dst->cwn[oc * 12 + k * 4 + c] =
            pk(conv_w[oc * 24 + (2 * c) * 3 + k], conv_w[oc * 24 + (2 * c + 1) * 3 + k]);
    }
    for (int j = tid; j < 256; j += 128) {
        const int f = j / 8, q = j % 8;
        dst->w1[j] = pk(w1[f * 16 + 2 * q], w1[f * 16 + 2 * q + 1]);
    }
    if (tid < 8)  dst->w2a[tid] = pk(0.5f * w2[4 * tid],     0.5f * w2[4 * tid + 2]); // col 0, halved
    if (tid < 8)  dst->w2b[tid] = pk(0.5f * w2[4 * tid + 1], 0.5f * w2[4 * tid + 3]); // col 1, halved
    if (tid < 16) dst->cbp[tid] = pk(conv_b[tid], 0.f);
    if (tid < 8)  dst->b1[tid]  = pk(b1[2 * tid], b1[2 * tid + 1]);
    if (tid == 0) { dst->b2[0] = pk(b2[0], 0.f); dst->b2[1] = pk(b2[1], 0.f); }
    if (tid < 8)  dst->g[tid]   = pk(ln_g[2 * tid], ln_g[2 * tid + 1]);
    if (tid < 8)  dst->bb[tid]  = pk(ln_b[2 * tid], ln_b[2 * tid + 1]);
}

__global__ __launch_bounds__(THREADS, 4)
void bimanual_kernel(const float* __restrict__ x, float* __restrict__ out)
{
    __shared__ __align__(16) u64 xs[ROWOFF(TILE + 2)];   // natural-order x tile (staggered)

    const int tid   = threadIdx.x;
    const int b     = blockIdx.y;
    const int tbase = blockIdx.x * TILE;

    // ---- stage x tile: straight 4x16B copy per row (natural channel order) ----
    for (int tt = tid; tt < TILE + 2; tt += THREADS) {
        const int t = tbase - 2 + tt;
        ulonglong2* row = (ulonglong2*)&xs[ROWOFF(tt)];
        if (t >= 0) {
            const ulonglong2* p = (const ulonglong2*)(x + ((size_t)b * T_ + t) * 16);
            row[0] = p[0]; row[1] = p[1]; row[2] = p[2]; row[3] = p[3];
        } else {
            row[0] = make_ulonglong2(0ull, 0ull);
            row[1] = make_ulonglong2(0ull, 0ull);
            row[2] = make_ulonglong2(0ull, 0ull);
            row[3] = make_ulonglong2(0ull, 0ull);
        }
    }
    __syncthreads();

    // ---- per-thread: ITEMS consecutive elements, window rows r0 .. r0+ITEMS+1 ----
    const int r0 = tid * ITEMS;

    // hidden accumulators: 8 packed output-pairs per element
    u64 hid[ITEMS][8];
    #pragma unroll
    for (int j = 0; j < 8; ++j) {
        const u64 bj = cW.b1[j];
        #pragma unroll
        for (int i = 0; i < ITEMS; ++i) hid[i][j] = bj;
    }

    // Scope the x window so it is dead after the conv loop (register pressure).
    {
        // xp[r][0..3] = L channels (ic pairs), xp[r][4..7] = R channels (ic pairs)
        u64 xp[ITEMS + 2][8];
        #pragma unroll
        for (int r = 0; r < ITEMS + 2; ++r) {
            const ulonglong2* row = (const ulonglong2*)&xs[ROWOFF(r0 + r)];
            #pragma unroll
            for (int q = 0; q < 4; ++q) {           // 4x LDS.128 per row, conflict-free
                const ulonglong2 v = row[q];
                xp[r][2 * q] = v.x; xp[r][2 * q + 1] = v.y;
            }
        }

        // ---- fused conv(+ReLU) -> rank-1 MLP update; ic-pair FFMA2, dedup LDC ----
        #pragma unroll
        for (int oc = 0; oc < 16; ++oc) {
            u64 aL[ITEMS], aR[ITEMS];
            {
                const u64 cb0 = cW.cbp[oc];          // (cb, 0): lane-sum absorbs bias
                #pragma unroll
                for (int i = 0; i < ITEMS; ++i) { aL[i] = cb0; aR[i] = cb0; }
            }
            #pragma unroll
            for (int k = 0; k < 3; ++k) {
                const ulonglong2* wp = (const ulonglong2*)&cW.cwn[oc * 12 + k * 4];
                const ulonglong2 w01 = wp[0];        // LDC.128: ic-pairs 0-1
                const ulonglong2 w23 = wp[1];        // LDC.128: ic-pairs 2-3
                #pragma unroll
                for (int i = 0; i < ITEMS; ++i) {
                    aL[i] = ffma2(xp[i + k][0], w01.x, aL[i]);
                    aL[i] = ffma2(xp[i + k][1], w01.y, aL[i]);
                    aL[i] = ffma2(xp[i + k][2], w23.x, aL[i]);
                    aL[i] = ffma2(xp[i + k][3], w23.y, aL[i]);
                    aR[i] = ffma2(xp[i + k][4], w01.x, aR[i]);
                    aR[i] = ffma2(xp[i + k][5], w01.y, aR[i]);
                    aR[i] = ffma2(xp[i + k][6], w23.x, aR[i]);
                    aR[i] = ffma2(xp[i + k][7], w23.y, aR[i]);
                }
            }
            // horizontal lane-sum (+ bias already inside) + ReLU + splat
            u64 vl[ITEMS], vr[ITEMS];
            #pragma unroll
            for (int i = 0; i < ITEMS; ++i) {
                float l0, l1, rr0, rr1;
                upk(aL[i], l0, l1); upk(aR[i], rr0, rr1);
                const float hl = fmaxf(l0 + l1, 0.f);
                const float hr = fmaxf(rr0 + rr1, 0.f);
                vl[i] = pk(hl, hl); vr[i] = pk(hr, hr);
            }
            // rank-1 update of hidden accs: hid += hl*w1[oc,:] + hr*w1[16+oc,:]
            const ulonglong2* wlr = (const ulonglong2*)&cW.w1[oc * 8];
            const ulonglong2* wrr = (const ulonglong2*)&cW.w1[(16 + oc) * 8];
            #pragma unroll
            for (int q = 0; q < 4; ++q) {
                const ulonglong2 wl = wlr[q];         // LDC.128
                const ulonglong2 wr = wrr[q];
                #pragma unroll
                for (int i = 0; i < ITEMS; ++i) {
                    hid[i][2 * q]     = ffma2(vl[i], wl.x, ffma2(vr[i], wr.x, hid[i][2 * q]));
                    hid[i][2 * q + 1] = ffma2(vl[i], wl.y, ffma2(vr[i], wr.y, hid[i][2 * q + 1]));
                }
            }
        }
    } // xp dies here

    // ---- logits: relu(h)*w2 == (h+|h|)*(w2/2); dual packed dot-product ----
    float a0v[ITEMS], a1v[ITEMS];
    {
        u64 accA[ITEMS], accB[ITEMS];
        #pragma unroll
        for (int i = 0; i < ITEMS; ++i) { accA[i] = cW.b2[0]; accB[i] = cW.b2[1]; }
        #pragma unroll
        for (int j = 0; j < 8; ++j) {
            const u64 wa = cW.w2a[j];                 // pre-halved
            const u64 wb = cW.w2b[j];
            #pragma unroll
            for (int i = 0; i < ITEMS; ++i) {
                const u64 h    = hid[i][j];
                const u64 habs = h & 0x7FFFFFFF7FFFFFFFull;   // packed |h| (2x LOP3)
                const u64 hsum = fadd2(h, habs);              // = 2*relu(h)
                accA[i] = ffma2(hsum, wa, accA[i]);
                accB[i] = ffma2(hsum, wb, accB[i]);
            }
        }
        #pragma unroll
        for (int i = 0; i < ITEMS; ++i) {
            float aLo, aHi, bLo, bHi;
            upk(accA[i], aLo, aHi); upk(accB[i], bLo, bHi);
            const float l0 = aLo + aHi;                    // b2[0] folded in aLo
            const float l1 = bLo + bHi;                    // b2[1] folded in bLo
            const float e = __expf(l1 - l0);
            a0v[i] = 1.f / (1.f + e);
            a1v[i] = e * a0v[i];
        }
    }

    // ---- gated residual + LayerNorm(16) + stores (natural channel order) ----
    #pragma unroll
    for (int i = 0; i < ITEMS; ++i) {
        const int tglob = tbase + r0 + i;
        const ulonglong2* xrow = (const ulonglong2*)&xs[ROWOFF(r0 + i + 2)];
        const u64 sp0 = pk(1.f + a0v[i], 1.f + a0v[i]);   // L channels scale
        const u64 sp1 = pk(1.f + a1v[i], 1.f + a1v[i]);   // R channels scale
        u64 yp[8];
        u64 sum = pk(0.f, 0.f);
        #pragma unroll
        for (int q = 0; q < 4; ++q) {
            const ulonglong2 v = xrow[q];
            const u64 s = (q < 2) ? sp0 : sp1;
            yp[2 * q]     = fmul2(v.x, s);
            yp[2 * q + 1] = fmul2(v.y, s);
            sum = fadd2(sum, yp[2 * q]);
            sum = fadd2(sum, yp[2 * q + 1]);
        }
        float sE, sO; upk(sum, sE, sO);                    // even/odd channel sums
        const float mu   = (sE + sO) * 0.0625f;
        const u64   nmup = pk(-mu, -mu);
        u64 var2 = pk(0.f, 0.f);
        u64 dp[8];
        #pragma unroll
        for (int c = 0; c < 8; ++c) { dp[c] = fadd2(yp[c], nmup); var2 = ffma2(dp[c], dp[c], var2); }
        float vE, vO; upk(var2, vE, vO);
        const float rs  = rsqrtf((vE + vO) * 0.0625f + 1e-5f);
        const u64   rsp = pk(rs, rs);

        // output pairs in natural order -> direct 16B stores, no unpack shuffle
        ulonglong2* outX = (ulonglong2*)(out + ((size_t)b * T_ + tglob) * 16);
        #pragma unroll
        for (int q = 0; q < 4; ++q) {
            const u64 oA = ffma2(fmul2(dp[2 * q],     rsp), cW.g[2 * q],     cW.bb[2 * q]);
            const u64 oB = ffma2(fmul2(dp[2 * q + 1], rsp), cW.g[2 * q + 1], cW.bb[2 * q + 1]);
            outX[q] = make_ulonglong2(oA, oB);
        }
        float2* outA = (float2*)(out + (size_t)B_ * T_ * 16 + ((size_t)b * T_ + tglob) * 2);
        *outA = make_float2(a0v[i], a1v[i]);
    }
}

extern "C" void kernel_launch(void* const* d_in, const int* in_sizes, int n_in,
                              void* d_out, int out_size)
{
    const float* x      = (const float*)d_in[0];
    const float* conv_w = (const float*)d_in[1];
    const float* conv_b = (const float*)d_in[2];
    const float* w1     = (const float*)d_in[3];
    const float* b1     = (const float*)d_in[4];
    const float* w2     = (const float*)d_in[5];
    const float* b2     = (const float*)d_in[6];
    const float* ln_g   = (const float*)d_in[7];
    const float* ln_b   = (const float*)d_in[8];

    // Prep writes packed weights DIRECTLY into cW's device backing store
    // (constant caches are invalidated at launch boundaries; the main kernel
    // is a separate, ordered launch). Graph: 2 nodes, no memcpy.
    void* cw_ptr = nullptr;
    cudaGetSymbolAddress(&cw_ptr, cW);
    prep_kernel<<<1, 128>>>((Wts*)cw_ptr, conv_w, conv_b, w1, b1, w2, b2, ln_g, ln_b);

    dim3 grid(T_ / TILE, B_);
    bimanual_kernel<<<grid, THREADS>>>(x, (float*)d_out);
}

// round 15
// speedup vs baseline: 1.0221x; 1.0193x over previous
#include <cuda_runtime.h>

#define B_      512
#define T_      4096
#define THREADS 128
#define ITEMS   2
#define TILE    (THREADS * ITEMS)   // 256 -> grid.x = 16 exact
// row offset in u64: 10r + 2*(r/2). All rows 16B-aligned; lane stride (r0=2*tid)
// = 22 u64 = 44 words == 12 (mod 32) -> LDS.128 8-lane phases conflict-free.
#define ROWOFF(r) ((r) * 10 + ((((r) >> 1)) << 1))

typedef unsigned long long u64;

// ---- packed f32x2 helpers (PTX-only path on sm_103a; ptxas won't auto-fuse) ----
__device__ __forceinline__ u64 pk(float lo, float hi) {
    u64 r; asm("mov.b64 %0,{%1,%2};" : "=l"(r) : "f"(lo), "f"(hi)); return r;
}
__device__ __forceinline__ void upk(u64 v, float& lo, float& hi) {
    asm("mov.b64 {%0,%1},%2;" : "=f"(lo), "=f"(hi) : "l"(v));
}
__device__ __forceinline__ u64 ffma2(u64 a, u64 b, u64 c) {
    u64 d; asm("fma.rn.f32x2 %0,%1,%2,%3;" : "=l"(d) : "l"(a), "l"(b), "l"(c)); return d;
}
__device__ __forceinline__ u64 fmul2(u64 a, u64 b) {
    u64 d; asm("mul.rn.f32x2 %0,%1,%2;" : "=l"(d) : "l"(a), "l"(b)); return d;
}
__device__ __forceinline__ u64 fadd2(u64 a, u64 b) {
    u64 d; asm("add.rn.f32x2 %0,%1,%2;" : "=l"(d) : "l"(a), "l"(b)); return d;
}

// ---- ALL weights in constant memory (LDC port; R7-R9: LDS offload regresses).
// Conv weights as GENUINE ic-pair packs (R11 dedup). w2 column-wise, PRE-HALVED
// for the relu(x)=0.5*(x+|x|) logits identity. Prep kernel writes DIRECTLY to
// this symbol's device backing (2-node graph, validated in R14).
struct __align__(16) Wts {
    u64 cwn[192];  // conv weights [oc][k][c]: pair c = (w[oc,2c,k], w[oc,2c+1,k])
    u64 w1[256];   // w1 as hidden-output pairs: w1[f][j] = (w1[f,2j], w1[f,2j+1])
    u64 w2a[8];    // 0.5 * w2 col 0 pairs
    u64 w2b[8];    // 0.5 * w2 col 1 pairs
    u64 cbp[16];   // conv bias as (cb, 0) pairs
    u64 b1[8];     // b1 output pairs
    u64 b2[2];     // (b2[0], 0), (b2[1], 0) — accumulator-init folding
    u64 g[8];      // ln gamma natural pairs (2c, 2c+1)
    u64 bb[8];     // ln beta  natural pairs (2c, 2c+1)
};
__constant__ Wts cW;

__global__ void prep_kernel(Wts* __restrict__ dst,
                            const float* __restrict__ conv_w, const float* __restrict__ conv_b,
                            const float* __restrict__ w1,     const float* __restrict__ b1,
                            const float* __restrict__ w2,     const float* __restrict__ b2,
                            const float* __restrict__ ln_g,   const float* __restrict__ ln_b)
{
    const int tid = threadIdx.x;
    // conv_w is (oc, ic, k): idx = oc*24 + ic*3 + k
    for (int j = tid; j < 192; j += 128) {
        const int oc = j / 12, r = j % 12, k = r / 4, c = r % 4;
        dst->cwn[oc * 12 + k * 4 + c] =
            pk(conv_w[oc * 24 + (2 * c) * 3 + k], conv_w[oc * 24 + (2 * c + 1) * 3 + k]);
    }
    for (int j = tid; j < 256; j += 128) {
        const int f = j / 8, q = j % 8;
        dst->w1[j] = pk(w1[f * 16 + 2 * q], w1[f * 16 + 2 * q + 1]);
    }
    if (tid < 8)  dst->w2a[tid] = pk(0.5f * w2[4 * tid],     0.5f * w2[4 * tid + 2]); // col 0, halved
    if (tid < 8)  dst->w2b[tid] = pk(0.5f * w2[4 * tid + 1], 0.5f * w2[4 * tid + 3]); // col 1, halved
    if (tid < 16) dst->cbp[tid] = pk(conv_b[tid], 0.f);
    if (tid < 8)  dst->b1[tid]  = pk(b1[2 * tid], b1[2 * tid + 1]);
    if (tid == 0) { dst->b2[0] = pk(b2[0], 0.f); dst->b2[1] = pk(b2[1], 0.f); }
    if (tid < 8)  dst->g[tid]   = pk(ln_g[2 * tid], ln_g[2 * tid + 1]);
    if (tid < 8)  dst->bb[tid]  = pk(ln_b[2 * tid], ln_b[2 * tid + 1]);
}

__global__ __launch_bounds__(THREADS, 4)
void bimanual_kernel(const float* __restrict__ x, float* __restrict__ out)
{
    __shared__ __align__(16) u64 xs[ROWOFF(TILE + 2)];   // natural-order x tile (staggered)

    const int tid   = threadIdx.x;
    const int b     = blockIdx.y;
    const int tbase = blockIdx.x * TILE;

    // ---- stage x tile: straight 4x16B copy per row (natural channel order) ----
    for (int tt = tid; tt < TILE + 2; tt += THREADS) {
        const int t = tbase - 2 + tt;
        ulonglong2* row = (ulonglong2*)&xs[ROWOFF(tt)];
        if (t >= 0) {
            const ulonglong2* p = (const ulonglong2*)(x + ((size_t)b * T_ + t) * 16);
            row[0] = p[0]; row[1] = p[1]; row[2] = p[2]; row[3] = p[3];
        } else {
            row[0] = make_ulonglong2(0ull, 0ull);
            row[1] = make_ulonglong2(0ull, 0ull);
            row[2] = make_ulonglong2(0ull, 0ull);
            row[3] = make_ulonglong2(0ull, 0ull);
        }
    }
    __syncthreads();

    // ---- per-thread: ITEMS consecutive elements, window rows r0 .. r0+ITEMS+1 ----
    const int r0 = tid * ITEMS;

    // hidden accumulators: 8 packed output-pairs per element
    u64 hid[ITEMS][8];
    #pragma unroll
    for (int j = 0; j < 8; ++j) {
        const u64 bj = cW.b1[j];
        #pragma unroll
        for (int i = 0; i < ITEMS; ++i) hid[i][j] = bj;
    }

    // Scope the x window so it is dead after the conv loop (register pressure).
    {
        // xp[r][0..3] = L channels (ic pairs), xp[r][4..7] = R channels (ic pairs)
        u64 xp[ITEMS + 2][8];
        #pragma unroll
        for (int r = 0; r < ITEMS + 2; ++r) {
            const ulonglong2* row = (const ulonglong2*)&xs[ROWOFF(r0 + r)];
            #pragma unroll
            for (int q = 0; q < 4; ++q) {           // 4x LDS.128 per row, conflict-free
                const ulonglong2 v = row[q];
                xp[r][2 * q] = v.x; xp[r][2 * q + 1] = v.y;
            }
        }

        // ---- fused conv(+ReLU) -> rank-1 MLP update; ic-pair FFMA2, dedup LDC ----
        // (R13 body exactly: aR zero-init + scalar cb re-add measured fastest.)
        #pragma unroll
        for (int oc = 0; oc < 16; ++oc) {
            u64 aL[ITEMS], aR[ITEMS];
            {
                const u64 cb0 = cW.cbp[oc];          // (cb, 0): bias folds into lane-sum
                #pragma unroll
                for (int i = 0; i < ITEMS; ++i) { aL[i] = cb0; aR[i] = pk(0.f, 0.f); }
            }
            #pragma unroll
            for (int k = 0; k < 3; ++k) {
                const ulonglong2* wp = (const ulonglong2*)&cW.cwn[oc * 12 + k * 4];
                const ulonglong2 w01 = wp[0];        // LDC.128: ic-pairs 0-1
                const ulonglong2 w23 = wp[1];        // LDC.128: ic-pairs 2-3
                #pragma unroll
                for (int i = 0; i < ITEMS; ++i) {
                    aL[i] = ffma2(xp[i + k][0], w01.x, aL[i]);
                    aL[i] = ffma2(xp[i + k][1], w01.y, aL[i]);
                    aL[i] = ffma2(xp[i + k][2], w23.x, aL[i]);
                    aL[i] = ffma2(xp[i + k][3], w23.y, aL[i]);
                    aR[i] = ffma2(xp[i + k][4], w01.x, aR[i]);
                    aR[i] = ffma2(xp[i + k][5], w01.y, aR[i]);
                    aR[i] = ffma2(xp[i + k][6], w23.x, aR[i]);
                    aR[i] = ffma2(xp[i + k][7], w23.y, aR[i]);
                }
            }
            // horizontal lane-sum + bias + ReLU + splat
            u64 vl[ITEMS], vr[ITEMS];
            {
                float cb; { float z; upk(cW.cbp[oc], cb, z); }
                #pragma unroll
                for (int i = 0; i < ITEMS; ++i) {
                    float l0, l1, rr0, rr1;
                    upk(aL[i], l0, l1); upk(aR[i], rr0, rr1);
                    const float hl = fmaxf(l0 + l1, 0.f);            // cb already in l0
                    const float hr = fmaxf(rr0 + rr1 + cb, 0.f);
                    vl[i] = pk(hl, hl); vr[i] = pk(hr, hr);
                }
            }
            // rank-1 update of hidden accs: hid += hl*w1[oc,:] + hr*w1[16+oc,:]
            const ulonglong2* wlr = (const ulonglong2*)&cW.w1[oc * 8];
            const ulonglong2* wrr = (const ulonglong2*)&cW.w1[(16 + oc) * 8];
            #pragma unroll
            for (int q = 0; q < 4; ++q) {
                const ulonglong2 wl = wlr[q];         // LDC.128
                const ulonglong2 wr = wrr[q];
                #pragma unroll
                for (int i = 0; i < ITEMS; ++i) {
                    hid[i][2 * q]     = ffma2(vl[i], wl.x, ffma2(vr[i], wr.x, hid[i][2 * q]));
                    hid[i][2 * q + 1] = ffma2(vl[i], wl.y, ffma2(vr[i], wr.y, hid[i][2 * q + 1]));
                }
            }
        }
    } // xp dies here

    // ---- logits: relu(h)*w2 == (h+|h|)*(w2/2); dual packed dot-product ----
    float a0v[ITEMS], a1v[ITEMS];
    {
        u64 accA[ITEMS], accB[ITEMS];
        #pragma unroll
        for (int i = 0; i < ITEMS; ++i) { accA[i] = cW.b2[0]; accB[i] = cW.b2[1]; }
        #pragma unroll
        for (int j = 0; j < 8; ++j) {
            const u64 wa = cW.w2a[j];                 // pre-halved
            const u64 wb = cW.w2b[j];
            #pragma unroll
            for (int i = 0; i < ITEMS; ++i) {
                const u64 h    = hid[i][j];
                const u64 habs = h & 0x7FFFFFFF7FFFFFFFull;   // packed |h| (2x LOP3)
                const u64 hsum = fadd2(h, habs);              // = 2*relu(h)
                accA[i] = ffma2(hsum, wa, accA[i]);
                accB[i] = ffma2(hsum, wb, accB[i]);
            }
        }
        #pragma unroll
        for (int i = 0; i < ITEMS; ++i) {
            float aLo, aHi, bLo, bHi;
            upk(accA[i], aLo, aHi); upk(accB[i], bLo, bHi);
            const float l0 = aLo + aHi;                    // b2[0] folded in aLo
            const float l1 = bLo + bHi;                    // b2[1] folded in bLo
            const float e = __expf(l1 - l0);
            a0v[i] = 1.f / (1.f + e);
            a1v[i] = e * a0v[i];
        }
    }

    // ---- gated residual + LayerNorm(16) + stores (natural channel order) ----
    #pragma unroll
    for (int i = 0; i < ITEMS; ++i) {
        const int tglob = tbase + r0 + i;
        const ulonglong2* xrow = (const ulonglong2*)&xs[ROWOFF(r0 + i + 2)];
        const u64 sp0 = pk(1.f + a0v[i], 1.f + a0v[i]);   // L channels scale
        const u64 sp1 = pk(1.f + a1v[i], 1.f + a1v[i]);   // R channels scale
        u64 yp[8];
        u64 sum = pk(0.f, 0.f);
        #pragma unroll
        for (int q = 0; q < 4; ++q) {
            const ulonglong2 v = xrow[q];
            const u64 s = (q < 2) ? sp0 : sp1;
            yp[2 * q]     = fmul2(v.x, s);
            yp[2 * q + 1] = fmul2(v.y, s);
            sum = fadd2(sum, yp[2 * q]);
            sum = fadd2(sum, yp[2 * q + 1]);
        }
        float sE, sO; upk(sum, sE, sO);                    // even/odd channel sums
        const float mu   = (sE + sO) * 0.0625f;
        const u64   nmup = pk(-mu, -mu);
        u64 var2 = pk(0.f, 0.f);
        u64 dp[8];
        #pragma unroll
        for (int c = 0; c < 8; ++c) { dp[c] = fadd2(yp[c], nmup); var2 = ffma2(dp[c], dp[c], var2); }
        float vE, vO; upk(var2, vE, vO);
        const float rs  = rsqrtf((vE + vO) * 0.0625f + 1e-5f);
        const u64   rsp = pk(rs, rs);

        // output pairs in natural order -> direct 16B stores, no unpack shuffle
        ulonglong2* outX = (ulonglong2*)(out + ((size_t)b * T_ + tglob) * 16);
        #pragma unroll
        for (int q = 0; q < 4; ++q) {
            const u64 oA = ffma2(fmul2(dp[2 * q],     rsp), cW.g[2 * q],     cW.bb[2 * q]);
            const u64 oB = ffma2(fmul2(dp[2 * q + 1], rsp), cW.g[2 * q + 1], cW.bb[2 * q + 1]);
            outX[q] = make_ulonglong2(oA, oB);
        }
        float2* outA = (float2*)(out + (size_t)B_ * T_ * 16 + ((size_t)b * T_ + tglob) * 2);
        *outA = make_float2(a0v[i], a1v[i]);
    }
}

extern "C" void kernel_launch(void* const* d_in, const int* in_sizes, int n_in,
                              void* d_out, int out_size)
{
    const float* x      = (const float*)d_in[0];
    const float* conv_w = (const float*)d_in[1];
    const float* conv_b = (const float*)d_in[2];
    const float* w1     = (const float*)d_in[3];
    const float* b1     = (const float*)d_in[4];
    const float* w2     = (const float*)d_in[5];
    const float* b2     = (const float*)d_in[6];
    const float* ln_g   = (const float*)d_in[7];
    const float* ln_b   = (const float*)d_in[8];

    // Prep writes packed weights DIRECTLY into cW's device backing store
    // (validated R14: constant cache coherent across graph-node launches).
    void* cw_ptr = nullptr;
    cudaGetSymbolAddress(&cw_ptr, cW);
    prep_kernel<<<1, 128>>>((Wts*)cw_ptr, conv_w, conv_b, w1, b1, w2, b2, ln_g, ln_b);

    dim3 grid(T_ / TILE, B_);
    bimanual_kernel<<<grid, THREADS>>>(x, (float*)d_out);
}